// round 1
// baseline (speedup 1.0000x reference)
#include <cuda_runtime.h>
#include <cuda_bf16.h>
#include <cstdint>

// Problem shape (fixed by the reference):
//   edges:     [1,000,000 x 64] f32   (d_in[0])
//   nodes:     [100,000 x 8]   f32    (d_in[1])  -- data unused, defines segment count
//   receivers: [1,000,000]     i32    (d_in[2])
//   out:       [100,000 x 64]  f32    segment_sum(edges, receivers)

static constexpr int N_EDGES = 1000000;
static constexpr int N_FEAT  = 64;
static constexpr int CHUNKS_PER_EDGE = N_FEAT / 4;   // 16 float4 chunks per edge

// --- Kernel 1: zero the output (harness poisons it to 0xAA) -----------------
__global__ void zero_out_kernel(float4* __restrict__ out, int n4) {
    int i = blockIdx.x * blockDim.x + threadIdx.x;
    if (i < n4) out[i] = make_float4(0.f, 0.f, 0.f, 0.f);
}

// --- Kernel 2: scatter-add ---------------------------------------------------
// One thread per float4 chunk: 16M threads total. Each warp covers exactly
// 2 edges (32 threads / 16 chunks), so the receivers load broadcasts well and
// edge loads are fully coalesced 128B transactions.
// atomicAdd with unused result -> RED.E.ADD.F32 (fire-and-forget to L2; the
// 25.6MB output lives entirely in L2).
__global__ void __launch_bounds__(256) scatter_add_kernel(
    const float4* __restrict__ edges4,   // [N_EDGES * 16] float4
    const int*    __restrict__ receivers,
    float*        __restrict__ out)      // [N_NODES * 64]
{
    int t = blockIdx.x * blockDim.x + threadIdx.x;   // 0 .. 16M-1
    int e = t >> 4;          // edge index
    int c = t & 15;          // chunk within edge (4 floats)

    int r = __ldg(&receivers[e]);
    float4 v = edges4[t];

    float* dst = out + (size_t)r * N_FEAT + c * 4;
    atomicAdd(dst + 0, v.x);
    atomicAdd(dst + 1, v.y);
    atomicAdd(dst + 2, v.z);
    atomicAdd(dst + 3, v.w);
}

extern "C" void kernel_launch(void* const* d_in, const int* in_sizes, int n_in,
                              void* d_out, int out_size)
{
    const float4* edges4    = (const float4*)d_in[0];
    const int*    receivers = (const int*)d_in[2];
    float*        out       = (float*)d_out;

    // Zero output: out_size = 6,400,000 floats = 1,600,000 float4
    int n4 = out_size / 4;
    int zb = (n4 + 255) / 256;
    zero_out_kernel<<<zb, 256>>>((float4*)out, n4);

    // Scatter: 16M threads, 256/block -> 65536 blocks (exact fit, no tail)
    int total_threads = N_EDGES * CHUNKS_PER_EDGE;     // 16,000,000
    int sb = (total_threads + 255) / 256;
    scatter_add_kernel<<<sb, 256>>>(edges4, receivers, out);
}

// round 4
// speedup vs baseline: 2.3463x; 2.3463x over previous
#include <cuda_runtime.h>
#include <cuda_bf16.h>
#include <cstdint>

// Problem shape (fixed by the reference):
//   edges:     [1,000,000 x 64] f32   (d_in[0])
//   nodes:     [100,000 x 8]   f32    (d_in[1])  -- data unused, defines segment count
//   receivers: [1,000,000]     i32    (d_in[2])
//   out:       [100,000 x 64]  f32    segment_sum(edges, receivers)

static constexpr int N_EDGES = 1000000;
static constexpr int N_FEAT  = 64;
static constexpr int CHUNKS_PER_EDGE = N_FEAT / 4;   // 16 float4 chunks per edge

// --- Kernel 1: zero the output (harness poisons it to 0xAA) -----------------
__global__ void zero_out_kernel(float4* __restrict__ out, int n4) {
    int i = blockIdx.x * blockDim.x + threadIdx.x;
    if (i < n4) out[i] = make_float4(0.f, 0.f, 0.f, 0.f);
}

// --- Kernel 2: scatter-add with 128-bit vector red-atomics ------------------
// One thread per float4 chunk: 16M threads. Each warp covers exactly 2 edges,
// so receivers loads broadcast and edge loads are fully coalesced 128B txns.
// Native atomicAdd(float4*, float4) (CUDA 12.8+, sm_90+) with discarded
// result compiles to ONE fire-and-forget 16B RED per chunk instead of 4
// scalar REDs -> 4x fewer LSU/L1tex wavefronts. The 25.6MB output lives in
// L2, so the adds resolve in the LTS atomic ALUs.
__global__ void __launch_bounds__(256) scatter_add_kernel(
    const float4* __restrict__ edges4,   // [N_EDGES * 16] float4
    const int*    __restrict__ receivers,
    float*        __restrict__ out)      // [N_NODES * 64]
{
    int t = blockIdx.x * blockDim.x + threadIdx.x;   // 0 .. 16M-1
    int e = t >> 4;          // edge index
    int c = t & 15;          // chunk within edge (4 floats)

    int r = __ldg(&receivers[e]);
    float4 v = edges4[t];

    float4* dst = (float4*)(out + (size_t)r * N_FEAT + c * 4);  // 16B-aligned
    atomicAdd(dst, v);   // result unused -> RED.E.ADD.F32.128
}

extern "C" void kernel_launch(void* const* d_in, const int* in_sizes, int n_in,
                              void* d_out, int out_size)
{
    const float4* edges4    = (const float4*)d_in[0];
    const int*    receivers = (const int*)d_in[2];
    float*        out       = (float*)d_out;

    // Zero output: out_size = 6,400,000 floats = 1,600,000 float4
    int n4 = out_size / 4;
    int zb = (n4 + 255) / 256;
    zero_out_kernel<<<zb, 256>>>((float4*)out, n4);

    // Scatter: 16M threads, 256/block
    int total_threads = N_EDGES * CHUNKS_PER_EDGE;     // 16,000,000
    int sb = (total_threads + 255) / 256;
    scatter_add_kernel<<<sb, 256>>>(edges4, receivers, out);
}

// round 5
// speedup vs baseline: 2.4892x; 1.0609x over previous
#include <cuda_runtime.h>
#include <cuda_bf16.h>
#include <cstdint>

// Problem shape (fixed by the reference):
//   edges:     [1,000,000 x 64] f32   (d_in[0])
//   nodes:     [100,000 x 8]   f32    (d_in[1])  -- data unused, defines segment count
//   receivers: [1,000,000]     i32    (d_in[2])
//   out:       [100,000 x 64]  f32    segment_sum(edges, receivers)

static constexpr int N_EDGES = 1000000;
static constexpr int N_FEAT  = 64;
static constexpr int CHUNKS_PER_EDGE = N_FEAT / 4;   // 16 float4 chunks per edge

// --- Kernel 1: zero the output (harness poisons it to 0xAA) -----------------
__global__ void zero_out_kernel(float4* __restrict__ out, int n4) {
    int i = blockIdx.x * blockDim.x + threadIdx.x;
    if (i < n4) out[i] = make_float4(0.f, 0.f, 0.f, 0.f);
}

// --- Kernel 2: scatter-add with 128-bit vector red-atomics ------------------
// One thread per float4 chunk: 16M threads; each warp covers exactly 2 edges
// (coalesced 128B edge loads, broadcast receivers loads).
//
// Key points:
//  * atomicAdd(float4*, float4) with discarded result -> one fire-and-forget
//    RED.E.ADD.F32.128 per chunk (4x fewer LSU wavefronts than scalar REDs).
//  * __ldcs on the edge stream -> ld.global.cs.v4.f32 (evict-first). The
//    256MB zero-reuse stream no longer thrashes the 25.6MB output region out
//    of L2, so the REDs resolve at L2-hit latency with no extra DRAM
//    read-modify traffic.
__global__ void __launch_bounds__(256) scatter_add_kernel(
    const float4* __restrict__ edges4,   // [N_EDGES * 16] float4
    const int*    __restrict__ receivers,
    float*        __restrict__ out)      // [N_NODES * 64]
{
    int t = blockIdx.x * blockDim.x + threadIdx.x;   // 0 .. 16M-1
    int e = t >> 4;          // edge index
    int c = t & 15;          // chunk within edge (4 floats)

    int r = __ldg(&receivers[e]);
    float4 v = __ldcs(&edges4[t]);       // streaming load, evict-first

    float4* dst = (float4*)(out + (size_t)r * N_FEAT + c * 4);  // 16B-aligned
    atomicAdd(dst, v);   // result unused -> RED.E.ADD.F32.128
}

extern "C" void kernel_launch(void* const* d_in, const int* in_sizes, int n_in,
                              void* d_out, int out_size)
{
    const float4* edges4    = (const float4*)d_in[0];
    const int*    receivers = (const int*)d_in[2];
    float*        out       = (float*)d_out;

    // Zero output: out_size = 6,400,000 floats = 1,600,000 float4
    int n4 = out_size / 4;
    int zb = (n4 + 255) / 256;
    zero_out_kernel<<<zb, 256>>>((float4*)out, n4);

    // Scatter: 16M threads, 256/block
    int total_threads = N_EDGES * CHUNKS_PER_EDGE;     // 16,000,000
    int sb = (total_threads + 255) / 256;
    scatter_add_kernel<<<sb, 256>>>(edges4, receivers, out);
}

// round 8
// speedup vs baseline: 2.5760x; 1.0349x over previous
#include <cuda_runtime.h>
#include <cuda_bf16.h>
#include <cstdint>

// Problem shape (fixed by the reference):
//   edges:     [1,000,000 x 64] f32   (d_in[0])
//   nodes:     [100,000 x 8]   f32    (d_in[1])  -- data unused, defines segment count
//   receivers: [1,000,000]     i32    (d_in[2])
//   out:       [100,000 x 64]  f32    segment_sum(edges, receivers)

static constexpr int N_EDGES = 1000000;
static constexpr int N_FEAT  = 64;
static constexpr int THREADS_PER_EDGE = 8;           // 2 float4 chunks per thread

// --- Kernel 1: zero the output (harness poisons it to 0xAA) -----------------
__global__ void zero_out_kernel(float4* __restrict__ out, int n4) {
    int i = blockIdx.x * blockDim.x + threadIdx.x;
    if (i < n4) out[i] = make_float4(0.f, 0.f, 0.f, 0.f);
}

// --- Kernel 2: scatter-add, 2 independent 128b chunks/thread ----------------
// Thread t handles edge e = t>>3, chunks c = t&7 and c+8.
//   * The two loads hit DIFFERENT 128B lines of the 256B edge row -> MLP_p1=2
//     (doubled outstanding loads per warp vs the 1-chunk version).
//   * Lanes 0-7 cover one full 128B line -> loads and REDs stay perfectly
//     coalesced per 8-lane group.
//   * atomicAdd(float4*, float4) with discarded result -> fire-and-forget
//     RED.E.ADD.F32.128 (4x fewer LSU wavefronts than scalar REDs).
//   * __ldcs keeps the 256MB zero-reuse edge stream evict-first so the
//     25.6MB output region stays L2-resident for the REDs.
__global__ void __launch_bounds__(256) scatter_add_kernel(
    const float4* __restrict__ edges4,   // [N_EDGES * 16] float4
    const int*    __restrict__ receivers,
    float*        __restrict__ out)      // [N_NODES * 64]
{
    int t = blockIdx.x * blockDim.x + threadIdx.x;   // 0 .. 8M-1
    int e = t >> 3;          // edge index
    int c = t & 7;           // chunk 0..7; thread also handles c+8

    int r = __ldg(&receivers[e]);
    const float4* src = edges4 + ((size_t)e << 4);
    float4 v0 = __ldcs(src + c);         // line 0 of the 256B edge row
    float4 v1 = __ldcs(src + c + 8);     // line 1 (independent -> MLP 2)

    float4* dst = (float4*)(out + (size_t)r * N_FEAT) + c;
    atomicAdd(dst,     v0);              // RED.E.ADD.F32.128
    atomicAdd(dst + 8, v1);
}

extern "C" void kernel_launch(void* const* d_in, const int* in_sizes, int n_in,
                              void* d_out, int out_size)
{
    const float4* edges4    = (const float4*)d_in[0];
    const int*    receivers = (const int*)d_in[2];
    float*        out       = (float*)d_out;

    // Zero output: out_size = 6,400,000 floats = 1,600,000 float4
    int n4 = out_size / 4;
    int zb = (n4 + 255) / 256;
    zero_out_kernel<<<zb, 256>>>((float4*)out, n4);

    // Scatter: 8M threads, 256/block -> 31250 blocks
    int total_threads = N_EDGES * THREADS_PER_EDGE;   // 8,000,000
    int sb = (total_threads + 255) / 256;
    scatter_add_kernel<<<sb, 256>>>(edges4, receivers, out);
}